// round 7
// baseline (speedup 1.0000x reference)
#include <cuda_runtime.h>
#include <cuda_bf16.h>
#include <math.h>

#define HWN 65536   // 256*256
#define HN  256
#define WN  256

typedef unsigned long long u64;

// ---------------- packed f32x2 helpers (FFMA2) ----------------
__device__ __forceinline__ u64 pk2(float x, float y) {
    u64 r; asm("mov.b64 %0, {%1,%2};" : "=l"(r) : "f"(x), "f"(y)); return r;
}
__device__ __forceinline__ float2 up2(u64 v) {
    float2 f; asm("mov.b64 {%0,%1}, %2;" : "=f"(f.x), "=f"(f.y) : "l"(v)); return f;
}
__device__ __forceinline__ u64 fma2(u64 a, u64 b, u64 c) {
    u64 d; asm("fma.rn.f32x2 %0, %1, %2, %3;" : "=l"(d) : "l"(a), "l"(b), "l"(c)); return d;
}
__device__ __forceinline__ u64 mul2(u64 a, u64 b) {
    u64 d; asm("mul.rn.f32x2 %0, %1, %2;" : "=l"(d) : "l"(a), "l"(b)); return d;
}

// ---------------- scratch (device globals; no allocation) ----------------
__device__ __align__(16) float g_xcl[HWN * 32];
__device__ __align__(16) float g_fcl[HWN * 32];
__device__ __align__(16) float g_t2[HWN * 16];
__device__ __align__(16) float g_fpre[HWN * 32];
__device__ __align__(16) float g_q[2][HWN * 32];
__device__ __align__(16) float g_kv[2][HWN * 64];
__device__ __align__(16) float g_attn[2][HWN * 32];
__device__ __align__(16) float g_oc[2][HWN * 32];
__device__ __align__(8) unsigned g_biasb[576 * 256];  // [k][q] bf16x2 (2 heads)
__device__ float g_part[256 * 64];
__device__ float g_stats[64];

__device__ __forceinline__ float geluf(float x) {
    float c = 0.7978845608028654f * (x + 0.044715f * x * x * x);
    return 0.5f * x * (1.0f + tanhf(c));
}

// ---------------- rel-pos bias gather: transpose to [k][q], pack bf16x2 ----------------
__global__ void k_bias(const int* __restrict__ rpi, const float* __restrict__ rpb) {
    int idx = blockIdx.x * 256 + threadIdx.x;   // idx = k*256 + q
    int k = idx >> 8, q = idx & 255;
    int r = rpi[q * 576 + k];
    __nv_bfloat162 h2 = __float22bfloat162_rn(make_float2(rpb[r * 2 + 0], rpb[r * 2 + 1]));
    g_biasb[idx] = *(unsigned*)&h2;
}

// ---------------- NCHW -> [p][c] transpose (smem tiled) ----------------
__global__ void k_transpose(const float* __restrict__ x) {
    __shared__ float s[32][33];
    int p0 = blockIdx.x * 32;
    int t = threadIdx.x;
    int cr = t >> 5, pr = t & 31;
    #pragma unroll
    for (int it = 0; it < 4; it++) {
        int cc = it * 8 + cr;
        s[cc][pr] = x[cc * HWN + p0 + pr];
    }
    __syncthreads();
    int pw = t >> 5, cw = t & 31;
    #pragma unroll
    for (int it = 0; it < 4; it++) {
        int pp = it * 8 + pw;
        g_xcl[(p0 + pp) * 32 + cw] = s[cw][pp];
    }
}

// ---------------- stem: conv1(3x3,1->8,relu) + conv2(1x1,8->16,relu) ----------------
__global__ void __launch_bounds__(128) k_stem1(const float* __restrict__ depth,
                                               const float* __restrict__ w1, const float* __restrict__ b1,
                                               const float* __restrict__ w2, const float* __restrict__ b2) {
    __shared__ float sw1[72], sb1[8], sw2[128], sb2[16];
    int t = threadIdx.x;
    if (t < 72) sw1[t] = w1[t];
    if (t < 8)  sb1[t] = b1[t];
    if (t < 128) sw2[t] = w2[t];
    if (t < 16) sb2[t] = b2[t];
    __syncthreads();
    int p = blockIdx.x * 128 + t;
    int y = p >> 8, x = p & 255;
    float d[9];
    #pragma unroll
    for (int dy = 0; dy < 3; dy++)
        #pragma unroll
        for (int dx = 0; dx < 3; dx++) {
            int yy = y + dy - 1, xx = x + dx - 1;
            d[dy * 3 + dx] = (yy >= 0 && yy < HN && xx >= 0 && xx < WN) ? depth[yy * WN + xx] : 0.f;
        }
    float t8[8];
    #pragma unroll
    for (int o = 0; o < 8; o++) {
        float acc = sb1[o];
        #pragma unroll
        for (int j = 0; j < 9; j++) acc += d[j] * sw1[o * 9 + j];
        t8[o] = fmaxf(acc, 0.f);
    }
    #pragma unroll
    for (int o = 0; o < 16; o++) {
        float acc = sb2[o];
        #pragma unroll
        for (int i = 0; i < 8; i++) acc += t8[i] * sw2[o * 8 + i];
        g_t2[p * 16 + o] = fmaxf(acc, 0.f);
    }
}

// ---------------- stem: conv3(3x3,16->16,relu) + conv4(1x1,16->32), FFMA2 ----------------
__global__ void __launch_bounds__(128) k_stem2(const float* __restrict__ w3, const float* __restrict__ b3,
                                               const float* __restrict__ w4, const float* __restrict__ b4) {
    __shared__ u64 sw3p[1152];
    __shared__ u64 sw4p[256];
    __shared__ float sb3[16], sb4[32];
    int t = threadIdx.x;
    for (int idx = t; idx < 1152; idx += 128) {
        int n = idx >> 7, rem = idx & 127, i = rem >> 3, op = rem & 7;
        sw3p[idx] = pk2(w3[(2 * op) * 144 + i * 9 + n], w3[(2 * op + 1) * 144 + i * 9 + n]);
    }
    for (int idx = t; idx < 256; idx += 128) {
        int i = idx >> 4, op = idx & 15;
        sw4p[idx] = pk2(w4[(2 * op) * 16 + i], w4[(2 * op + 1) * 16 + i]);
    }
    if (t < 16) sb3[t] = b3[t];
    if (t < 32) sb4[t] = b4[t];
    __syncthreads();
    int p = blockIdx.x * 128 + t;
    int y = p >> 8, x = p & 255;
    u64 acc2[8];
    #pragma unroll
    for (int op = 0; op < 8; op++) acc2[op] = pk2(sb3[2 * op], sb3[2 * op + 1]);
    for (int dy = 0; dy < 3; dy++) {
        int yy = y + dy - 1;
        if (yy < 0 || yy >= HN) continue;
        for (int dx = 0; dx < 3; dx++) {
            int xx = x + dx - 1;
            if (xx < 0 || xx >= WN) continue;
            int n = dy * 3 + dx;
            const float4* s4 = (const float4*)(g_t2 + (yy * WN + xx) * 16);
            float in[16];
            #pragma unroll
            for (int u = 0; u < 4; u++) {
                float4 v = s4[u];
                in[u * 4] = v.x; in[u * 4 + 1] = v.y; in[u * 4 + 2] = v.z; in[u * 4 + 3] = v.w;
            }
            #pragma unroll
            for (int i = 0; i < 16; i++) {
                u64 ii = pk2(in[i], in[i]);
                const u64* wrow = sw3p + n * 128 + i * 8;
                #pragma unroll
                for (int op = 0; op < 8; op++) acc2[op] = fma2(ii, wrow[op], acc2[op]);
            }
        }
    }
    float t16[16];
    #pragma unroll
    for (int op = 0; op < 8; op++) {
        float2 f = up2(acc2[op]);
        t16[2 * op] = fmaxf(f.x, 0.f); t16[2 * op + 1] = fmaxf(f.y, 0.f);
    }
    u64 a4[16];
    #pragma unroll
    for (int op = 0; op < 16; op++) a4[op] = pk2(sb4[2 * op], sb4[2 * op + 1]);
    #pragma unroll
    for (int i = 0; i < 16; i++) {
        u64 ii = pk2(t16[i], t16[i]);
        const u64* wrow = sw4p + i * 16;
        #pragma unroll
        for (int op = 0; op < 16; op++) a4[op] = fma2(ii, wrow[op], a4[op]);
    }
    float2* o2 = (float2*)(g_fpre + p * 32);
    #pragma unroll
    for (int op = 0; op < 16; op++) o2[op] = up2(a4[op]);
}

// ---------------- instance norm: deterministic 2-stage reduction ----------------
__global__ void k_reduce() {
    int t = threadIdx.x;
    int c = t & 31, g = t >> 5;
    int base = blockIdx.x * 256;
    float s = 0.f, s2 = 0.f;
    for (int i = 0; i < 32; i++) {
        float v = g_fpre[(base + g * 32 + i) * 32 + c];
        s += v; s2 += v * v;
    }
    __shared__ float ss[256], sq[256];
    ss[t] = s; sq[t] = s2;
    __syncthreads();
    if (g == 0) {
        for (int gg = 1; gg < 8; gg++) { s += ss[gg * 32 + c]; s2 += sq[gg * 32 + c]; }
        g_part[blockIdx.x * 64 + c] = s;
        g_part[blockIdx.x * 64 + 32 + c] = s2;
    }
}

__global__ void k_finalize() {
    int t = threadIdx.x;  // 64
    float s = 0.f;
    for (int b = 0; b < 256; b++) s += g_part[b * 64 + t];
    g_stats[t] = s;
}

__global__ void k_stemnorm(const float* __restrict__ in_g, const float* __restrict__ in_b) {
    __shared__ float smean[32], srstd[32], sg[32], sb[32];
    int t = threadIdx.x;
    if (t < 32) {
        float mean = g_stats[t] * (1.f / 65536.f);
        float var = g_stats[32 + t] * (1.f / 65536.f) - mean * mean;
        smean[t] = mean;
        srstd[t] = rsqrtf(var + 1e-5f);
        sg[t] = in_g[t]; sb[t] = in_b[t];
    }
    __syncthreads();
    int p = blockIdx.x * 256 + t;
    const float4* s4 = (const float4*)(g_fpre + p * 32);
    float4* o4 = (float4*)(g_fcl + p * 32);
    #pragma unroll
    for (int u = 0; u < 8; u++) {
        float4 v = s4[u];
        float4 o;
        int c = u * 4;
        o.x = (v.x - smean[c])     * srstd[c]     * sg[c]     + sb[c];
        o.y = (v.y - smean[c + 1]) * srstd[c + 1] * sg[c + 1] + sb[c + 1];
        o.z = (v.z - smean[c + 2]) * srstd[c + 2] * sg[c + 2] + sb[c + 2];
        o.w = (v.w - smean[c + 3]) * srstd[c + 3] * sg[c + 3] + sb[c + 3];
        o4[u] = o;
    }
}

// ---------------- LN + q / kv projections (FFMA2) ----------------
__global__ void __launch_bounds__(256) k_lnproj(int which,
        const float* __restrict__ n1g, const float* __restrict__ n1b,
        const float* __restrict__ wq, const float* __restrict__ bq,
        const float* __restrict__ wkv, const float* __restrict__ bkv) {
    const float* src = which ? g_fcl : g_xcl;
    float* qout = which ? g_q[1] : g_q[0];
    float* kvout = which ? g_kv[1] : g_kv[0];
    __shared__ __align__(16) float swqT[1024];
    __shared__ __align__(16) float swkvT[2048];
    __shared__ float sbq[32], sbkv[64], sg[32], sb[32];
    int t = threadIdx.x;
    for (int idx = t; idx < 1024; idx += 256) { int i = idx >> 5, j = idx & 31; swqT[j * 32 + i] = wq[idx]; }
    for (int idx = t; idx < 2048; idx += 256) { int i = idx >> 6, j = idx & 63; swkvT[j * 32 + i] = wkv[idx]; }
    if (t < 32) { sbq[t] = bq[t]; sg[t] = n1g[t]; sb[t] = n1b[t]; }
    if (t < 64) sbkv[t] = bkv[t];
    __syncthreads();
    int p = blockIdx.x * 256 + t;
    float v[32];
    const float4* s4 = (const float4*)(src + p * 32);
    float s = 0.f, s2 = 0.f;
    #pragma unroll
    for (int u = 0; u < 8; u++) {
        float4 x4 = s4[u];
        v[u * 4] = x4.x; v[u * 4 + 1] = x4.y; v[u * 4 + 2] = x4.z; v[u * 4 + 3] = x4.w;
    }
    #pragma unroll
    for (int i = 0; i < 32; i++) { s += v[i]; s2 += v[i] * v[i]; }
    float m = s * (1.f / 32.f);
    float var = s2 * (1.f / 32.f) - m * m;
    float r = rsqrtf(var + 1e-5f);
    u64 v2[16];
    #pragma unroll
    for (int i = 0; i < 16; i++) {
        float a = (v[2 * i] - m) * r * sg[2 * i] + sb[2 * i];
        float b = (v[2 * i + 1] - m) * r * sg[2 * i + 1] + sb[2 * i + 1];
        v2[i] = pk2(a, b);
    }
    float o[32];
    #pragma unroll
    for (int j = 0; j < 32; j++) {
        const ulonglong2* w8 = (const ulonglong2*)(swqT + j * 32);
        u64 a = 0ull;
        #pragma unroll
        for (int u = 0; u < 8; u++) {
            ulonglong2 w = w8[u];
            a = fma2(v2[2 * u], w.x, a);
            a = fma2(v2[2 * u + 1], w.y, a);
        }
        float2 f = up2(a);
        o[j] = sbq[j] + f.x + f.y;
    }
    float4* qo = (float4*)(qout + p * 32);
    #pragma unroll
    for (int u = 0; u < 8; u++) qo[u] = make_float4(o[u * 4], o[u * 4 + 1], o[u * 4 + 2], o[u * 4 + 3]);

    #pragma unroll
    for (int half = 0; half < 2; half++) {
        #pragma unroll
        for (int j = 0; j < 32; j++) {
            int jj = half * 32 + j;
            const ulonglong2* w8 = (const ulonglong2*)(swkvT + jj * 32);
            u64 a = 0ull;
            #pragma unroll
            for (int u = 0; u < 8; u++) {
                ulonglong2 w = w8[u];
                a = fma2(v2[2 * u], w.x, a);
                a = fma2(v2[2 * u + 1], w.y, a);
            }
            float2 f = up2(a);
            o[j] = sbkv[jj] + f.x + f.y;
        }
        float4* ko = (float4*)(kvout + p * 64 + half * 32);
        #pragma unroll
        for (int u = 0; u < 8; u++) ko[u] = make_float4(o[u * 4], o[u * 4 + 1], o[u * 4 + 2], o[u * 4 + 3]);
    }
}

// ---------------- overlapping-window cross attention ----------------
// 128 threads/block, each thread owns 2 adjacent queries (2t, 2t+1).
// K/V smem rows are loaded once per thread per key and reused for both queries.
#define SM_UPDATE(mm, ll, acc, sc, vbase)                      \
    do {                                                       \
        if ((sc) > (mm)) {                                     \
            float _r = __expf((mm) - (sc));                    \
            (ll) *= _r;                                        \
            u64 _r2 = pk2(_r, _r);                             \
            _Pragma("unroll")                                  \
            for (int _i = 0; _i < 8; _i++) acc[_i] = mul2(acc[_i], _r2); \
            (mm) = (sc);                                       \
        }                                                      \
        float _e = __expf((sc) - (mm));                        \
        (ll) += _e;                                            \
        u64 _e2 = pk2(_e, _e);                                 \
        _Pragma("unroll")                                      \
        for (int _i = 0; _i < 8; _i++) acc[_i] = fma2(_e2, (vbase)[_i], acc[_i]); \
    } while (0)

__global__ void __launch_bounds__(128) k_attn() {
    int call = blockIdx.x >> 8;
    int win = blockIdx.x & 255;
    int wy = win >> 4, wx = win & 15;
    const float* qbuf = call ? g_q[1] : g_q[0];
    const float* kvbuf = call ? g_kv[0] : g_kv[1];
    float* obuf = call ? g_attn[1] : g_attn[0];

    int t = threadIdx.x;                 // 0..127
    int qidx = 2 * t;                    // query a = qidx, query b = qidx+1 (same row)
    int qy = qidx >> 4, qx = qidx & 15;
    int qpa = (wy * 16 + qy) * WN + (wx * 16 + qx);   // qpb = qpa + 1

    u64 qa[16], qb[16];
    {
        u64 qs = pk2(0.25f, 0.25f);
        const ulonglong2* q8a = (const ulonglong2*)(qbuf + qpa * 32);
        const ulonglong2* q8b = (const ulonglong2*)(qbuf + (qpa + 1) * 32);
        #pragma unroll
        for (int u = 0; u < 8; u++) {
            ulonglong2 va = q8a[u], vb = q8b[u];
            qa[2 * u] = mul2(va.x, qs); qa[2 * u + 1] = mul2(va.y, qs);
            qb[2 * u] = mul2(vb.x, qs); qb[2 * u + 1] = mul2(vb.y, qs);
        }
    }
    float mA0 = -1e30f, lA0 = 0.f, mA1 = -1e30f, lA1 = 0.f;
    float mB0 = -1e30f, lB0 = 0.f, mB1 = -1e30f, lB1 = 0.f;
    u64 accA0[8], accA1[8], accB0[8], accB1[8];
    #pragma unroll
    for (int i = 0; i < 8; i++) { accA0[i] = 0ull; accA1[i] = 0ull; accB0[i] = 0ull; accB1[i] = 0ull; }

    __shared__ __align__(16) float sk[96 * 32];
    __shared__ __align__(16) float sv[96 * 32];

    const unsigned* bbase = g_biasb + 2 * t;

    for (int c0 = 0; c0 < 576; c0 += 96) {
        __syncthreads();
        // stage 96 keys x 32ch of K and V (zero-padded at image border)
        for (int idx = t; idx < 768; idx += 128) {
            int kk = idx >> 3, u = idx & 7;
            int key = c0 + kk;
            int ky = (key * 2731) >> 16;            // key / 24
            int kx2 = key - ky * 24;
            int gy = wy * 16 - 4 + ky, gx = wx * 16 - 4 + kx2;
            float4 kf = make_float4(0.f, 0.f, 0.f, 0.f);
            float4 vf = make_float4(0.f, 0.f, 0.f, 0.f);
            if ((unsigned)gy < 256u && (unsigned)gx < 256u) {
                const float4* src = (const float4*)(kvbuf + (gy * WN + gx) * 64);
                kf = src[u]; vf = src[8 + u];
            }
            ((float4*)sk)[idx] = kf;
            ((float4*)sv)[idx] = vf;
        }
        __syncthreads();
        const unsigned* bptr = bbase + c0 * 256;
        #pragma unroll 2
        for (int kk = 0; kk < 96; kk++) {
            uint2 ub = *(const uint2*)(bptr + kk * 256);
            float2 bA = __bfloat1622float2(*(const __nv_bfloat162*)&ub.x);
            float2 bB = __bfloat1622float2(*(const __nv_bfloat162*)&ub.y);
            const ulonglong2* k8 = (const ulonglong2*)(sk + kk * 32);
            u64 kx[16];
            #pragma unroll
            for (int u = 0; u < 8; u++) { ulonglong2 w = k8[u]; kx[2 * u] = w.x; kx[2 * u + 1] = w.y; }
            u64 dA0 = 0ull, dA1 = 0ull, dB0 = 0ull, dB1 = 0ull;
            #pragma unroll
            for (int u = 0; u < 8; u++) {
                dA0 = fma2(qa[u], kx[u], dA0);
                dA1 = fma2(qa[8 + u], kx[8 + u], dA1);
                dB0 = fma2(qb[u], kx[u], dB0);
                dB1 = fma2(qb[8 + u], kx[8 + u], dB1);
            }
            float2 f;
            f = up2(dA0); float sA0 = bA.x + f.x + f.y;
            f = up2(dA1); float sA1 = bA.y + f.x + f.y;
            f = up2(dB0); float sB0 = bB.x + f.x + f.y;
            f = up2(dB1); float sB1 = bB.y + f.x + f.y;
            const ulonglong2* v8 = (const ulonglong2*)(sv + kk * 32);
            u64 vx[16];
            #pragma unroll
            for (int u = 0; u < 8; u++) { ulonglong2 w = v8[u]; vx[2 * u] = w.x; vx[2 * u + 1] = w.y; }
            SM_UPDATE(mA0, lA0, accA0, sA0, vx);
            SM_UPDATE(mA1, lA1, accA1, sA1, (vx + 8));
            SM_UPDATE(mB0, lB0, accB0, sB0, vx);
            SM_UPDATE(mB1, lB1, accB1, sB1, (vx + 8));
        }
    }
    float rA0 = 1.f / lA0, rA1 = 1.f / lA1, rB0 = 1.f / lB0, rB1 = 1.f / lB1;
    float2* oA = (float2*)(obuf + qpa * 32);
    float2* oB = (float2*)(obuf + (qpa + 1) * 32);
    #pragma unroll
    for (int i = 0; i < 8; i++) {
        float2 f = up2(accA0[i]); oA[i] = make_float2(f.x * rA0, f.y * rA0);
    }
    #pragma unroll
    for (int i = 0; i < 8; i++) {
        float2 f = up2(accA1[i]); oA[8 + i] = make_float2(f.x * rA1, f.y * rA1);
    }
    #pragma unroll
    for (int i = 0; i < 8; i++) {
        float2 f = up2(accB0[i]); oB[i] = make_float2(f.x * rB0, f.y * rB0);
    }
    #pragma unroll
    for (int i = 0; i < 8; i++) {
        float2 f = up2(accB1[i]); oB[8 + i] = make_float2(f.x * rB1, f.y * rB1);
    }
}

// ---------------- proj + shortcut + LN2 + MLP (FFMA2) ----------------
__global__ void __launch_bounds__(256) k_post(int which,
        const float* __restrict__ wp, const float* __restrict__ bp,
        const float* __restrict__ n2g, const float* __restrict__ n2b,
        const float* __restrict__ mw1, const float* __restrict__ mb1,
        const float* __restrict__ mw2, const float* __restrict__ mb2) {
    const float* ain = which ? g_attn[1] : g_attn[0];
    const float* shc = which ? g_fcl : g_xcl;
    float* outb = which ? g_oc[1] : g_oc[0];
    __shared__ __align__(16) float swpT[1024];
    __shared__ __align__(16) float smw1T[2048];
    __shared__ __align__(16) float smw2[2048];
    __shared__ float sbp[32], sb1[64], sb2[32], sg[32], sb[32];
    int t = threadIdx.x;
    for (int idx = t; idx < 1024; idx += 256) { int i = idx >> 5, j = idx & 31; swpT[j * 32 + i] = wp[idx]; }
    for (int idx = t; idx < 2048; idx += 256) { int i = idx >> 6, k = idx & 63; smw1T[k * 32 + i] = mw1[idx]; }
    for (int idx = t; idx < 2048; idx += 256) smw2[idx] = mw2[idx];
    if (t < 32) { sbp[t] = bp[t]; sb2[t] = mb2[t]; sg[t] = n2g[t]; sb[t] = n2b[t]; }
    if (t < 64) sb1[t] = mb1[t];
    __syncthreads();
    int p = blockIdx.x * 256 + t;
    u64 a2[16];
    {
        const ulonglong2* a8 = (const ulonglong2*)(ain + p * 32);
        #pragma unroll
        for (int u = 0; u < 8; u++) {
            ulonglong2 v = a8[u];
            a2[2 * u] = v.x; a2[2 * u + 1] = v.y;
        }
    }
    float o[32];
    const float4* s4 = (const float4*)(shc + p * 32);
    #pragma unroll
    for (int u = 0; u < 8; u++) {
        float4 v = s4[u];
        o[u * 4] = v.x + sbp[u * 4]; o[u * 4 + 1] = v.y + sbp[u * 4 + 1];
        o[u * 4 + 2] = v.z + sbp[u * 4 + 2]; o[u * 4 + 3] = v.w + sbp[u * 4 + 3];
    }
    #pragma unroll
    for (int j = 0; j < 32; j++) {
        const ulonglong2* w8 = (const ulonglong2*)(swpT + j * 32);
        u64 acc = 0ull;
        #pragma unroll
        for (int u = 0; u < 8; u++) {
            ulonglong2 w = w8[u];
            acc = fma2(a2[2 * u], w.x, acc);
            acc = fma2(a2[2 * u + 1], w.y, acc);
        }
        float2 f = up2(acc);
        o[j] += f.x + f.y;
    }
    float s = 0.f, s2 = 0.f;
    #pragma unroll
    for (int i = 0; i < 32; i++) { s += o[i]; s2 += o[i] * o[i]; }
    float m = s * (1.f / 32.f);
    float var = s2 * (1.f / 32.f) - m * m;
    float r = rsqrtf(var + 1e-5f);
    u64 n2[16];
    #pragma unroll
    for (int i = 0; i < 16; i++) {
        float a = (o[2 * i] - m) * r * sg[2 * i] + sb[2 * i];
        float b = (o[2 * i + 1] - m) * r * sg[2 * i + 1] + sb[2 * i + 1];
        n2[i] = pk2(a, b);
    }
    u64 o2[16];
    #pragma unroll
    for (int i = 0; i < 16; i++) o2[i] = pk2(o[2 * i] + sb2[2 * i], o[2 * i + 1] + sb2[2 * i + 1]);
    for (int k = 0; k < 64; k++) {
        const ulonglong2* w8 = (const ulonglong2*)(smw1T + k * 32);
        u64 acc = 0ull;
        #pragma unroll
        for (int u = 0; u < 8; u++) {
            ulonglong2 w = w8[u];
            acc = fma2(n2[2 * u], w.x, acc);
            acc = fma2(n2[2 * u + 1], w.y, acc);
        }
        float2 f = up2(acc);
        float hv = geluf(sb1[k] + f.x + f.y);
        u64 hv2 = pk2(hv, hv);
        const ulonglong2* w2 = (const ulonglong2*)(smw2 + k * 32);
        #pragma unroll
        for (int u = 0; u < 8; u++) {
            ulonglong2 w = w2[u];
            o2[2 * u] = fma2(hv2, w.x, o2[2 * u]);
            o2[2 * u + 1] = fma2(hv2, w.y, o2[2 * u + 1]);
        }
    }
    float2* ob = (float2*)(outb + p * 32);
    #pragma unroll
    for (int i = 0; i < 16; i++) ob[i] = up2(o2[i]);
}

// ---------------- final: out1 + out2 + x, back to NCHW ----------------
__global__ void k_final(const float* __restrict__ x, float* __restrict__ out) {
    __shared__ float s[32][33];
    int p0 = blockIdx.x * 32;
    int t = threadIdx.x;
    int pr = t >> 5, cr = t & 31;
    #pragma unroll
    for (int it = 0; it < 4; it++) {
        int pp = it * 8 + pr;
        int idx = (p0 + pp) * 32 + cr;
        s[pp][cr] = g_oc[0][idx] + g_oc[1][idx];
    }
    __syncthreads();
    int cw = t >> 5, pw = t & 31;
    #pragma unroll
    for (int it = 0; it < 4; it++) {
        int cc = it * 8 + cw;
        int gi = cc * HWN + p0 + pw;
        out[gi] = s[pw][cc] + x[gi];
    }
}

extern "C" void kernel_launch(void* const* d_in, const int* in_sizes, int n_in,
                              void* d_out, int out_size) {
    const float* x    = (const float*)d_in[0];
    const float* depth= (const float*)d_in[1];
    const int*   rpi  = (const int*)d_in[2];
    const float* cw1  = (const float*)d_in[3];  const float* cb1 = (const float*)d_in[4];
    const float* cw2  = (const float*)d_in[5];  const float* cb2 = (const float*)d_in[6];
    const float* cw3  = (const float*)d_in[7];  const float* cb3 = (const float*)d_in[8];
    const float* cw4  = (const float*)d_in[9];  const float* cb4 = (const float*)d_in[10];
    const float* in_g = (const float*)d_in[11]; const float* in_b = (const float*)d_in[12];
    const float* n1g  = (const float*)d_in[13]; const float* n1b = (const float*)d_in[14];
    const float* wq   = (const float*)d_in[15]; const float* bq  = (const float*)d_in[16];
    const float* wkv  = (const float*)d_in[17]; const float* bkv = (const float*)d_in[18];
    const float* rpb  = (const float*)d_in[19];
    const float* wp   = (const float*)d_in[20]; const float* bp  = (const float*)d_in[21];
    const float* n2g  = (const float*)d_in[22]; const float* n2b = (const float*)d_in[23];
    const float* mw1  = (const float*)d_in[24]; const float* mb1 = (const float*)d_in[25];
    const float* mw2  = (const float*)d_in[26]; const float* mb2 = (const float*)d_in[27];
    float* out = (float*)d_out;

    k_bias<<<576, 256>>>(rpi, rpb);
    k_transpose<<<2048, 256>>>(x);
    k_stem1<<<512, 128>>>(depth, cw1, cb1, cw2, cb2);
    k_stem2<<<512, 128>>>(cw3, cb3, cw4, cb4);
    k_reduce<<<256, 256>>>();
    k_finalize<<<1, 64>>>();
    k_stemnorm<<<256, 256>>>(in_g, in_b);
    k_lnproj<<<256, 256>>>(0, n1g, n1b, wq, bq, wkv, bkv);
    k_lnproj<<<256, 256>>>(1, n1g, n1b, wq, bq, wkv, bkv);
    k_attn<<<512, 128>>>();
    k_post<<<256, 256>>>(0, wp, bp, n2g, n2b, mw1, mb1, mw2, mb2);
    k_post<<<256, 256>>>(1, wp, bp, n2g, n2b, mw1, mb1, mw2, mb2);
    k_final<<<2048, 256>>>(x, out);
}

// round 8
// speedup vs baseline: 1.1910x; 1.1910x over previous
#include <cuda_runtime.h>
#include <cuda_bf16.h>
#include <math.h>

#define HWN 65536   // 256*256
#define HN  256
#define WN  256

typedef unsigned long long u64;

// ---------------- packed f32x2 helpers (FFMA2) ----------------
__device__ __forceinline__ u64 pk2(float x, float y) {
    u64 r; asm("mov.b64 %0, {%1,%2};" : "=l"(r) : "f"(x), "f"(y)); return r;
}
__device__ __forceinline__ float2 up2(u64 v) {
    float2 f; asm("mov.b64 {%0,%1}, %2;" : "=f"(f.x), "=f"(f.y) : "l"(v)); return f;
}
__device__ __forceinline__ u64 fma2(u64 a, u64 b, u64 c) {
    u64 d; asm("fma.rn.f32x2 %0, %1, %2, %3;" : "=l"(d) : "l"(a), "l"(b), "l"(c)); return d;
}
__device__ __forceinline__ u64 mul2(u64 a, u64 b) {
    u64 d; asm("mul.rn.f32x2 %0, %1, %2;" : "=l"(d) : "l"(a), "l"(b)); return d;
}

// ---------------- scratch (device globals; no allocation) ----------------
__device__ __align__(16) float g_xcl[HWN * 32];
__device__ __align__(16) float g_fcl[HWN * 32];
__device__ __align__(16) float g_t2[HWN * 16];
__device__ __align__(16) float g_fpre[HWN * 32];
__device__ __align__(16) float g_q[2][HWN * 32];
__device__ __align__(16) float g_kv[2][HWN * 64];
__device__ __align__(16) float g_attn[2][HWN * 32];
__device__ __align__(16) float g_oc[2][HWN * 32];
__device__ __align__(8) unsigned g_biasb[576 * 256];  // [k][q] bf16x2 (2 heads)
__device__ float g_part[256 * 64];
__device__ float g_stats[64];

__device__ __forceinline__ float geluf(float x) {
    float c = 0.7978845608028654f * (x + 0.044715f * x * x * x);
    return 0.5f * x * (1.0f + tanhf(c));
}

// ---------------- rel-pos bias gather: transpose to [k][q], pack bf16x2 ----------------
__global__ void k_bias(const int* __restrict__ rpi, const float* __restrict__ rpb) {
    int idx = blockIdx.x * 256 + threadIdx.x;   // idx = k*256 + q
    int k = idx >> 8, q = idx & 255;
    int r = rpi[q * 576 + k];
    __nv_bfloat162 h2 = __float22bfloat162_rn(make_float2(rpb[r * 2 + 0], rpb[r * 2 + 1]));
    g_biasb[idx] = *(unsigned*)&h2;
}

// ---------------- NCHW -> [p][c] transpose (smem tiled) ----------------
__global__ void k_transpose(const float* __restrict__ x) {
    __shared__ float s[32][33];
    int p0 = blockIdx.x * 32;
    int t = threadIdx.x;
    int cr = t >> 5, pr = t & 31;
    #pragma unroll
    for (int it = 0; it < 4; it++) {
        int cc = it * 8 + cr;
        s[cc][pr] = x[cc * HWN + p0 + pr];
    }
    __syncthreads();
    int pw = t >> 5, cw = t & 31;
    #pragma unroll
    for (int it = 0; it < 4; it++) {
        int pp = it * 8 + pw;
        g_xcl[(p0 + pp) * 32 + cw] = s[cw][pp];
    }
}

// ---------------- stem: conv1(3x3,1->8,relu) + conv2(1x1,8->16,relu) ----------------
__global__ void __launch_bounds__(128) k_stem1(const float* __restrict__ depth,
                                               const float* __restrict__ w1, const float* __restrict__ b1,
                                               const float* __restrict__ w2, const float* __restrict__ b2) {
    __shared__ float sw1[72], sb1[8], sw2[128], sb2[16];
    int t = threadIdx.x;
    if (t < 72) sw1[t] = w1[t];
    if (t < 8)  sb1[t] = b1[t];
    if (t < 128) sw2[t] = w2[t];
    if (t < 16) sb2[t] = b2[t];
    __syncthreads();
    int p = blockIdx.x * 128 + t;
    int y = p >> 8, x = p & 255;
    float d[9];
    #pragma unroll
    for (int dy = 0; dy < 3; dy++)
        #pragma unroll
        for (int dx = 0; dx < 3; dx++) {
            int yy = y + dy - 1, xx = x + dx - 1;
            d[dy * 3 + dx] = (yy >= 0 && yy < HN && xx >= 0 && xx < WN) ? depth[yy * WN + xx] : 0.f;
        }
    float t8[8];
    #pragma unroll
    for (int o = 0; o < 8; o++) {
        float acc = sb1[o];
        #pragma unroll
        for (int j = 0; j < 9; j++) acc += d[j] * sw1[o * 9 + j];
        t8[o] = fmaxf(acc, 0.f);
    }
    #pragma unroll
    for (int o = 0; o < 16; o++) {
        float acc = sb2[o];
        #pragma unroll
        for (int i = 0; i < 8; i++) acc += t8[i] * sw2[o * 8 + i];
        g_t2[p * 16 + o] = fmaxf(acc, 0.f);
    }
}

// ---------------- stem: conv3(3x3,16->16,relu) + conv4(1x1,16->32), FFMA2 ----------------
__global__ void __launch_bounds__(128) k_stem2(const float* __restrict__ w3, const float* __restrict__ b3,
                                               const float* __restrict__ w4, const float* __restrict__ b4) {
    __shared__ u64 sw3p[1152];
    __shared__ u64 sw4p[256];
    __shared__ float sb3[16], sb4[32];
    int t = threadIdx.x;
    for (int idx = t; idx < 1152; idx += 128) {
        int n = idx >> 7, rem = idx & 127, i = rem >> 3, op = rem & 7;
        sw3p[idx] = pk2(w3[(2 * op) * 144 + i * 9 + n], w3[(2 * op + 1) * 144 + i * 9 + n]);
    }
    for (int idx = t; idx < 256; idx += 128) {
        int i = idx >> 4, op = idx & 15;
        sw4p[idx] = pk2(w4[(2 * op) * 16 + i], w4[(2 * op + 1) * 16 + i]);
    }
    if (t < 16) sb3[t] = b3[t];
    if (t < 32) sb4[t] = b4[t];
    __syncthreads();
    int p = blockIdx.x * 128 + t;
    int y = p >> 8, x = p & 255;
    u64 acc2[8];
    #pragma unroll
    for (int op = 0; op < 8; op++) acc2[op] = pk2(sb3[2 * op], sb3[2 * op + 1]);
    for (int dy = 0; dy < 3; dy++) {
        int yy = y + dy - 1;
        if (yy < 0 || yy >= HN) continue;
        for (int dx = 0; dx < 3; dx++) {
            int xx = x + dx - 1;
            if (xx < 0 || xx >= WN) continue;
            int n = dy * 3 + dx;
            const float4* s4 = (const float4*)(g_t2 + (yy * WN + xx) * 16);
            float in[16];
            #pragma unroll
            for (int u = 0; u < 4; u++) {
                float4 v = s4[u];
                in[u * 4] = v.x; in[u * 4 + 1] = v.y; in[u * 4 + 2] = v.z; in[u * 4 + 3] = v.w;
            }
            #pragma unroll
            for (int i = 0; i < 16; i++) {
                u64 ii = pk2(in[i], in[i]);
                const u64* wrow = sw3p + n * 128 + i * 8;
                #pragma unroll
                for (int op = 0; op < 8; op++) acc2[op] = fma2(ii, wrow[op], acc2[op]);
            }
        }
    }
    float t16[16];
    #pragma unroll
    for (int op = 0; op < 8; op++) {
        float2 f = up2(acc2[op]);
        t16[2 * op] = fmaxf(f.x, 0.f); t16[2 * op + 1] = fmaxf(f.y, 0.f);
    }
    u64 a4[16];
    #pragma unroll
    for (int op = 0; op < 16; op++) a4[op] = pk2(sb4[2 * op], sb4[2 * op + 1]);
    #pragma unroll
    for (int i = 0; i < 16; i++) {
        u64 ii = pk2(t16[i], t16[i]);
        const u64* wrow = sw4p + i * 16;
        #pragma unroll
        for (int op = 0; op < 16; op++) a4[op] = fma2(ii, wrow[op], a4[op]);
    }
    float2* o2 = (float2*)(g_fpre + p * 32);
    #pragma unroll
    for (int op = 0; op < 16; op++) o2[op] = up2(a4[op]);
}

// ---------------- instance norm: deterministic 2-stage reduction ----------------
__global__ void k_reduce() {
    int t = threadIdx.x;
    int c = t & 31, g = t >> 5;
    int base = blockIdx.x * 256;
    float s = 0.f, s2 = 0.f;
    for (int i = 0; i < 32; i++) {
        float v = g_fpre[(base + g * 32 + i) * 32 + c];
        s += v; s2 += v * v;
    }
    __shared__ float ss[256], sq[256];
    ss[t] = s; sq[t] = s2;
    __syncthreads();
    if (g == 0) {
        for (int gg = 1; gg < 8; gg++) { s += ss[gg * 32 + c]; s2 += sq[gg * 32 + c]; }
        g_part[blockIdx.x * 64 + c] = s;
        g_part[blockIdx.x * 64 + 32 + c] = s2;
    }
}

__global__ void k_finalize() {
    int t = threadIdx.x;  // 64
    float s = 0.f;
    for (int b = 0; b < 256; b++) s += g_part[b * 64 + t];
    g_stats[t] = s;
}

__global__ void k_stemnorm(const float* __restrict__ in_g, const float* __restrict__ in_b) {
    __shared__ float smean[32], srstd[32], sg[32], sb[32];
    int t = threadIdx.x;
    if (t < 32) {
        float mean = g_stats[t] * (1.f / 65536.f);
        float var = g_stats[32 + t] * (1.f / 65536.f) - mean * mean;
        smean[t] = mean;
        srstd[t] = rsqrtf(var + 1e-5f);
        sg[t] = in_g[t]; sb[t] = in_b[t];
    }
    __syncthreads();
    int p = blockIdx.x * 256 + t;
    const float4* s4 = (const float4*)(g_fpre + p * 32);
    float4* o4 = (float4*)(g_fcl + p * 32);
    #pragma unroll
    for (int u = 0; u < 8; u++) {
        float4 v = s4[u];
        float4 o;
        int c = u * 4;
        o.x = (v.x - smean[c])     * srstd[c]     * sg[c]     + sb[c];
        o.y = (v.y - smean[c + 1]) * srstd[c + 1] * sg[c + 1] + sb[c + 1];
        o.z = (v.z - smean[c + 2]) * srstd[c + 2] * sg[c + 2] + sb[c + 2];
        o.w = (v.w - smean[c + 3]) * srstd[c + 3] * sg[c + 3] + sb[c + 3];
        o4[u] = o;
    }
}

// ---------------- LN + q / kv projections (FFMA2) ----------------
__global__ void __launch_bounds__(256) k_lnproj(int which,
        const float* __restrict__ n1g, const float* __restrict__ n1b,
        const float* __restrict__ wq, const float* __restrict__ bq,
        const float* __restrict__ wkv, const float* __restrict__ bkv) {
    const float* src = which ? g_fcl : g_xcl;
    float* qout = which ? g_q[1] : g_q[0];
    float* kvout = which ? g_kv[1] : g_kv[0];
    __shared__ __align__(16) float swqT[1024];
    __shared__ __align__(16) float swkvT[2048];
    __shared__ float sbq[32], sbkv[64], sg[32], sb[32];
    int t = threadIdx.x;
    for (int idx = t; idx < 1024; idx += 256) { int i = idx >> 5, j = idx & 31; swqT[j * 32 + i] = wq[idx]; }
    for (int idx = t; idx < 2048; idx += 256) { int i = idx >> 6, j = idx & 63; swkvT[j * 32 + i] = wkv[idx]; }
    if (t < 32) { sbq[t] = bq[t]; sg[t] = n1g[t]; sb[t] = n1b[t]; }
    if (t < 64) sbkv[t] = bkv[t];
    __syncthreads();
    int p = blockIdx.x * 256 + t;
    float v[32];
    const float4* s4 = (const float4*)(src + p * 32);
    float s = 0.f, s2 = 0.f;
    #pragma unroll
    for (int u = 0; u < 8; u++) {
        float4 x4 = s4[u];
        v[u * 4] = x4.x; v[u * 4 + 1] = x4.y; v[u * 4 + 2] = x4.z; v[u * 4 + 3] = x4.w;
    }
    #pragma unroll
    for (int i = 0; i < 32; i++) { s += v[i]; s2 += v[i] * v[i]; }
    float m = s * (1.f / 32.f);
    float var = s2 * (1.f / 32.f) - m * m;
    float r = rsqrtf(var + 1e-5f);
    u64 v2[16];
    #pragma unroll
    for (int i = 0; i < 16; i++) {
        float a = (v[2 * i] - m) * r * sg[2 * i] + sb[2 * i];
        float b = (v[2 * i + 1] - m) * r * sg[2 * i + 1] + sb[2 * i + 1];
        v2[i] = pk2(a, b);
    }
    float o[32];
    #pragma unroll
    for (int j = 0; j < 32; j++) {
        const ulonglong2* w8 = (const ulonglong2*)(swqT + j * 32);
        u64 a = 0ull;
        #pragma unroll
        for (int u = 0; u < 8; u++) {
            ulonglong2 w = w8[u];
            a = fma2(v2[2 * u], w.x, a);
            a = fma2(v2[2 * u + 1], w.y, a);
        }
        float2 f = up2(a);
        o[j] = sbq[j] + f.x + f.y;
    }
    float4* qo = (float4*)(qout + p * 32);
    #pragma unroll
    for (int u = 0; u < 8; u++) qo[u] = make_float4(o[u * 4], o[u * 4 + 1], o[u * 4 + 2], o[u * 4 + 3]);

    #pragma unroll
    for (int half = 0; half < 2; half++) {
        #pragma unroll
        for (int j = 0; j < 32; j++) {
            int jj = half * 32 + j;
            const ulonglong2* w8 = (const ulonglong2*)(swkvT + jj * 32);
            u64 a = 0ull;
            #pragma unroll
            for (int u = 0; u < 8; u++) {
                ulonglong2 w = w8[u];
                a = fma2(v2[2 * u], w.x, a);
                a = fma2(v2[2 * u + 1], w.y, a);
            }
            float2 f = up2(a);
            o[j] = sbkv[jj] + f.x + f.y;
        }
        float4* ko = (float4*)(kvout + p * 64 + half * 32);
        #pragma unroll
        for (int u = 0; u < 8; u++) ko[u] = make_float4(o[u * 4], o[u * 4 + 1], o[u * 4 + 2], o[u * 4 + 3]);
    }
}

// ---------------- overlapping-window cross attention ----------------
// 256 threads = 1 query each. Double-buffered K/V smem chunks (96 keys),
// bias LDGs batched 4-wide for MLP, online softmax with FFMA2.
#define KEYSTEP(kk, ub)                                                            \
    do {                                                                           \
        float2 bb = __bfloat1622float2(*(const __nv_bfloat162*)&(ub));             \
        const ulonglong2* k8 = (const ulonglong2*)(skb + (kk) * 32);               \
        u64 d0 = 0ull, d1 = 0ull;                                                  \
        _Pragma("unroll")                                                          \
        for (int u = 0; u < 4; u++) {                                              \
            ulonglong2 kd = k8[u];                                                 \
            d0 = fma2(qv2[2 * u], kd.x, d0);                                       \
            d0 = fma2(qv2[2 * u + 1], kd.y, d0);                                   \
        }                                                                          \
        _Pragma("unroll")                                                          \
        for (int u = 4; u < 8; u++) {                                              \
            ulonglong2 kd = k8[u];                                                 \
            d1 = fma2(qv2[2 * u], kd.x, d1);                                       \
            d1 = fma2(qv2[2 * u + 1], kd.y, d1);                                   \
        }                                                                          \
        float2 f0 = up2(d0), f1 = up2(d1);                                         \
        float s0 = bb.x + f0.x + f0.y;                                             \
        float s1 = bb.y + f1.x + f1.y;                                             \
        const ulonglong2* v8 = (const ulonglong2*)(svb + (kk) * 32);               \
        if (s0 > m0) {                                                             \
            float sc = __expf(m0 - s0); l0 *= sc;                                  \
            u64 sc2 = pk2(sc, sc);                                                 \
            _Pragma("unroll")                                                      \
            for (int i = 0; i < 8; i++) acc0[i] = mul2(acc0[i], sc2);              \
            m0 = s0;                                                               \
        }                                                                          \
        float e0 = __expf(s0 - m0); l0 += e0;                                      \
        u64 e02 = pk2(e0, e0);                                                     \
        _Pragma("unroll")                                                          \
        for (int u = 0; u < 4; u++) {                                              \
            ulonglong2 vd = v8[u];                                                 \
            acc0[2 * u] = fma2(e02, vd.x, acc0[2 * u]);                            \
            acc0[2 * u + 1] = fma2(e02, vd.y, acc0[2 * u + 1]);                    \
        }                                                                          \
        if (s1 > m1) {                                                             \
            float sc = __expf(m1 - s1); l1 *= sc;                                  \
            u64 sc2 = pk2(sc, sc);                                                 \
            _Pragma("unroll")                                                      \
            for (int i = 0; i < 8; i++) acc1[i] = mul2(acc1[i], sc2);              \
            m1 = s1;                                                               \
        }                                                                          \
        float e1 = __expf(s1 - m1); l1 += e1;                                      \
        u64 e12 = pk2(e1, e1);                                                     \
        _Pragma("unroll")                                                          \
        for (int u = 0; u < 4; u++) {                                              \
            ulonglong2 vd = v8[4 + u];                                             \
            acc1[2 * u] = fma2(e12, vd.x, acc1[2 * u]);                            \
            acc1[2 * u + 1] = fma2(e12, vd.y, acc1[2 * u + 1]);                    \
        }                                                                          \
    } while (0)

__global__ void __launch_bounds__(256) k_attn() {
    int call = blockIdx.x >> 8;
    int win = blockIdx.x & 255;
    int wy = win >> 4, wx = win & 15;
    const float* qbuf = call ? g_q[1] : g_q[0];
    const float* kvbuf = call ? g_kv[0] : g_kv[1];
    float* obuf = call ? g_attn[1] : g_attn[0];

    int t = threadIdx.x;
    int qy = t >> 4, qx = t & 15;
    int qp = (wy * 16 + qy) * WN + (wx * 16 + qx);
    u64 qv2[16];
    {
        const ulonglong2* q8 = (const ulonglong2*)(qbuf + qp * 32);
        u64 qs = pk2(0.25f, 0.25f);
        #pragma unroll
        for (int u = 0; u < 8; u++) {
            ulonglong2 v = q8[u];
            qv2[2 * u] = mul2(v.x, qs);
            qv2[2 * u + 1] = mul2(v.y, qs);
        }
    }
    float m0 = -1e30f, l0 = 0.f, m1 = -1e30f, l1 = 0.f;
    u64 acc0[8], acc1[8];
    #pragma unroll
    for (int i = 0; i < 8; i++) { acc0[i] = 0ull; acc1[i] = 0ull; }

    __shared__ __align__(16) float sk[2][96 * 32];
    __shared__ __align__(16) float sv[2][96 * 32];

    int base_gy = wy * 16 - 4, base_gx = wx * 16 - 4;

    // stage chunk 0 directly
    #pragma unroll
    for (int it = 0; it < 3; it++) {
        int idx = t + it * 256;
        int kk = idx >> 3, u = idx & 7;
        int ky = (kk * 2731) >> 16;
        int kx2 = kk - ky * 24;
        int gy = base_gy + ky, gx = base_gx + kx2;
        float4 kf = make_float4(0.f, 0.f, 0.f, 0.f);
        float4 vf = make_float4(0.f, 0.f, 0.f, 0.f);
        if ((unsigned)gy < 256u && (unsigned)gx < 256u) {
            const float4* src = (const float4*)(kvbuf + (gy * WN + gx) * 64);
            kf = src[u]; vf = src[8 + u];
        }
        ((float4*)sk[0])[idx] = kf;
        ((float4*)sv[0])[idx] = vf;
    }
    __syncthreads();

    for (int ci = 0; ci < 6; ci++) {
        int buf = ci & 1;
        float4 pkf[3], pvf[3];
        if (ci < 5) {
            int c0n = (ci + 1) * 96;
            #pragma unroll
            for (int it = 0; it < 3; it++) {
                int idx = t + it * 256;
                int key = c0n + (idx >> 3);
                int u = idx & 7;
                int ky = (key * 2731) >> 16;
                int kx2 = key - ky * 24;
                int gy = base_gy + ky, gx = base_gx + kx2;
                pkf[it] = make_float4(0.f, 0.f, 0.f, 0.f);
                pvf[it] = make_float4(0.f, 0.f, 0.f, 0.f);
                if ((unsigned)gy < 256u && (unsigned)gx < 256u) {
                    const float4* src = (const float4*)(kvbuf + (gy * WN + gx) * 64);
                    pkf[it] = src[u]; pvf[it] = src[8 + u];
                }
            }
        }
        const float* skb = sk[buf];
        const float* svb = sv[buf];
        const unsigned* bptr = g_biasb + (ci * 96) * 256 + t;
        #pragma unroll 1
        for (int g = 0; g < 24; g++) {
            unsigned ub0 = bptr[(4 * g + 0) * 256];
            unsigned ub1 = bptr[(4 * g + 1) * 256];
            unsigned ub2 = bptr[(4 * g + 2) * 256];
            unsigned ub3 = bptr[(4 * g + 3) * 256];
            KEYSTEP(4 * g + 0, ub0);
            KEYSTEP(4 * g + 1, ub1);
            KEYSTEP(4 * g + 2, ub2);
            KEYSTEP(4 * g + 3, ub3);
        }
        __syncthreads();
        if (ci < 5) {
            int nbuf = buf ^ 1;
            #pragma unroll
            for (int it = 0; it < 3; it++) {
                int idx = t + it * 256;
                ((float4*)sk[nbuf])[idx] = pkf[it];
                ((float4*)sv[nbuf])[idx] = pvf[it];
            }
            __syncthreads();
        }
    }
    float r0 = 1.f / l0, r1 = 1.f / l1;
    float2* o2 = (float2*)(obuf + qp * 32);
    #pragma unroll
    for (int i = 0; i < 8; i++) {
        float2 f = up2(acc0[i]);
        o2[i] = make_float2(f.x * r0, f.y * r0);
    }
    #pragma unroll
    for (int i = 0; i < 8; i++) {
        float2 f = up2(acc1[i]);
        o2[8 + i] = make_float2(f.x * r1, f.y * r1);
    }
}

// ---------------- proj + shortcut + LN2 + MLP (FFMA2) ----------------
__global__ void __launch_bounds__(256) k_post(int which,
        const float* __restrict__ wp, const float* __restrict__ bp,
        const float* __restrict__ n2g, const float* __restrict__ n2b,
        const float* __restrict__ mw1, const float* __restrict__ mb1,
        const float* __restrict__ mw2, const float* __restrict__ mb2) {
    const float* ain = which ? g_attn[1] : g_attn[0];
    const float* shc = which ? g_fcl : g_xcl;
    float* outb = which ? g_oc[1] : g_oc[0];
    __shared__ __align__(16) float swpT[1024];
    __shared__ __align__(16) float smw1T[2048];
    __shared__ __align__(16) float smw2[2048];
    __shared__ float sbp[32], sb1[64], sb2[32], sg[32], sb[32];
    int t = threadIdx.x;
    for (int idx = t; idx < 1024; idx += 256) { int i = idx >> 5, j = idx & 31; swpT[j * 32 + i] = wp[idx]; }
    for (int idx = t; idx < 2048; idx += 256) { int i = idx >> 6, k = idx & 63; smw1T[k * 32 + i] = mw1[idx]; }
    for (int idx = t; idx < 2048; idx += 256) smw2[idx] = mw2[idx];
    if (t < 32) { sbp[t] = bp[t]; sb2[t] = mb2[t]; sg[t] = n2g[t]; sb[t] = n2b[t]; }
    if (t < 64) sb1[t] = mb1[t];
    __syncthreads();
    int p = blockIdx.x * 256 + t;
    u64 a2[16];
    {
        const ulonglong2* a8 = (const ulonglong2*)(ain + p * 32);
        #pragma unroll
        for (int u = 0; u < 8; u++) {
            ulonglong2 v = a8[u];
            a2[2 * u] = v.x; a2[2 * u + 1] = v.y;
        }
    }
    float o[32];
    const float4* s4 = (const float4*)(shc + p * 32);
    #pragma unroll
    for (int u = 0; u < 8; u++) {
        float4 v = s4[u];
        o[u * 4] = v.x + sbp[u * 4]; o[u * 4 + 1] = v.y + sbp[u * 4 + 1];
        o[u * 4 + 2] = v.z + sbp[u * 4 + 2]; o[u * 4 + 3] = v.w + sbp[u * 4 + 3];
    }
    #pragma unroll
    for (int j = 0; j < 32; j++) {
        const ulonglong2* w8 = (const ulonglong2*)(swpT + j * 32);
        u64 acc = 0ull;
        #pragma unroll
        for (int u = 0; u < 8; u++) {
            ulonglong2 w = w8[u];
            acc = fma2(a2[2 * u], w.x, acc);
            acc = fma2(a2[2 * u + 1], w.y, acc);
        }
        float2 f = up2(acc);
        o[j] += f.x + f.y;
    }
    float s = 0.f, s2 = 0.f;
    #pragma unroll
    for (int i = 0; i < 32; i++) { s += o[i]; s2 += o[i] * o[i]; }
    float m = s * (1.f / 32.f);
    float var = s2 * (1.f / 32.f) - m * m;
    float r = rsqrtf(var + 1e-5f);
    u64 n2[16];
    #pragma unroll
    for (int i = 0; i < 16; i++) {
        float a = (o[2 * i] - m) * r * sg[2 * i] + sb[2 * i];
        float b = (o[2 * i + 1] - m) * r * sg[2 * i + 1] + sb[2 * i + 1];
        n2[i] = pk2(a, b);
    }
    u64 o2[16];
    #pragma unroll
    for (int i = 0; i < 16; i++) o2[i] = pk2(o[2 * i] + sb2[2 * i], o[2 * i + 1] + sb2[2 * i + 1]);
    for (int k = 0; k < 64; k++) {
        const ulonglong2* w8 = (const ulonglong2*)(smw1T + k * 32);
        u64 acc = 0ull;
        #pragma unroll
        for (int u = 0; u < 8; u++) {
            ulonglong2 w = w8[u];
            acc = fma2(n2[2 * u], w.x, acc);
            acc = fma2(n2[2 * u + 1], w.y, acc);
        }
        float2 f = up2(acc);
        float hv = geluf(sb1[k] + f.x + f.y);
        u64 hv2 = pk2(hv, hv);
        const ulonglong2* w2 = (const ulonglong2*)(smw2 + k * 32);
        #pragma unroll
        for (int u = 0; u < 8; u++) {
            ulonglong2 w = w2[u];
            o2[2 * u] = fma2(hv2, w.x, o2[2 * u]);
            o2[2 * u + 1] = fma2(hv2, w.y, o2[2 * u + 1]);
        }
    }
    float2* ob = (float2*)(outb + p * 32);
    #pragma unroll
    for (int i = 0; i < 16; i++) ob[i] = up2(o2[i]);
}

// ---------------- final: out1 + out2 + x, back to NCHW ----------------
__global__ void k_final(const float* __restrict__ x, float* __restrict__ out) {
    __shared__ float s[32][33];
    int p0 = blockIdx.x * 32;
    int t = threadIdx.x;
    int pr = t >> 5, cr = t & 31;
    #pragma unroll
    for (int it = 0; it < 4; it++) {
        int pp = it * 8 + pr;
        int idx = (p0 + pp) * 32 + cr;
        s[pp][cr] = g_oc[0][idx] + g_oc[1][idx];
    }
    __syncthreads();
    int cw = t >> 5, pw = t & 31;
    #pragma unroll
    for (int it = 0; it < 4; it++) {
        int cc = it * 8 + cw;
        int gi = cc * HWN + p0 + pw;
        out[gi] = s[pw][cc] + x[gi];
    }
}

extern "C" void kernel_launch(void* const* d_in, const int* in_sizes, int n_in,
                              void* d_out, int out_size) {
    const float* x    = (const float*)d_in[0];
    const float* depth= (const float*)d_in[1];
    const int*   rpi  = (const int*)d_in[2];
    const float* cw1  = (const float*)d_in[3];  const float* cb1 = (const float*)d_in[4];
    const float* cw2  = (const float*)d_in[5];  const float* cb2 = (const float*)d_in[6];
    const float* cw3  = (const float*)d_in[7];  const float* cb3 = (const float*)d_in[8];
    const float* cw4  = (const float*)d_in[9];  const float* cb4 = (const float*)d_in[10];
    const float* in_g = (const float*)d_in[11]; const float* in_b = (const float*)d_in[12];
    const float* n1g  = (const float*)d_in[13]; const float* n1b = (const float*)d_in[14];
    const float* wq   = (const float*)d_in[15]; const float* bq  = (const float*)d_in[16];
    const float* wkv  = (const float*)d_in[17]; const float* bkv = (const float*)d_in[18];
    const float* rpb  = (const float*)d_in[19];
    const float* wp   = (const float*)d_in[20]; const float* bp  = (const float*)d_in[21];
    const float* n2g  = (const float*)d_in[22]; const float* n2b = (const float*)d_in[23];
    const float* mw1  = (const float*)d_in[24]; const float* mb1 = (const float*)d_in[25];
    const float* mw2  = (const float*)d_in[26]; const float* mb2 = (const float*)d_in[27];
    float* out = (float*)d_out;

    k_bias<<<576, 256>>>(rpi, rpb);
    k_transpose<<<2048, 256>>>(x);
    k_stem1<<<512, 128>>>(depth, cw1, cb1, cw2, cb2);
    k_stem2<<<512, 128>>>(cw3, cb3, cw4, cb4);
    k_reduce<<<256, 256>>>();
    k_finalize<<<1, 64>>>();
    k_stemnorm<<<256, 256>>>(in_g, in_b);
    k_lnproj<<<256, 256>>>(0, n1g, n1b, wq, bq, wkv, bkv);
    k_lnproj<<<256, 256>>>(1, n1g, n1b, wq, bq, wkv, bkv);
    k_attn<<<512, 256>>>();
    k_post<<<256, 256>>>(0, wp, bp, n2g, n2b, mw1, mb1, mw2, mb2);
    k_post<<<256, 256>>>(1, wp, bp, n2g, n2b, mw1, mb1, mw2, mb2);
    k_final<<<2048, 256>>>(x, out);
}